// round 14
// baseline (speedup 1.0000x reference)
#include <cuda_runtime.h>
#include <cuda_bf16.h>
#include <math.h>

// Problem constants
#define B_  8
#define L_  256
#define DM_ 1024
#define DI_ 2048
#define N_  16
#define K_  4
#define NL_ 4
#define DTR_ 128
#define P_  97
#define M_TOK (B_*L_)          // 2048 token rows
#define XPW_ (DTR_ + 2*N_)     // 160

// GEMM tiling
#define BM 128
#define BN 128
#define BK 16
#define SST 132                // smem row stride in words ([kp][m] layout, kp = k/2)

// ---------------- scratch (static device globals; no allocation) ----------------
__device__ __align__(16) float g_h [M_TOK*DM_];
__device__ __align__(16) float g_x [M_TOK*DM_];
__device__ __align__(16) float g_xz[M_TOK*2*DI_];
__device__ __align__(16) float g_xb[M_TOK*DI_];
__device__ __align__(16) float g_xp[M_TOK*XPW_];
__device__ __align__(16) float g_dl[M_TOK*DI_];
__device__ __align__(16) float g_y [M_TOK*DI_];
__device__ __align__(16) float g_fin[B_*DM_];

// ---------------- small utils ----------------
__global__ void zero_k(float* __restrict__ p, int n4) {
    int i = blockIdx.x * 256 + threadIdx.x;
    if (i < n4) reinterpret_cast<float4*>(p)[i] = make_float4(0,0,0,0);
}

// ---------------- embedding ----------------
__global__ void embed_k(const int* __restrict__ tok, const float* __restrict__ te,
                        const float* __restrict__ pe, float* __restrict__ h) {
    int row = blockIdx.x;
    int l = row & (L_ - 1);
    int t = tok[row];
    const float* tsrc = te + (long)t * DM_;
    const float* psrc = pe + (long)l * DM_;
    float* dst = h + (long)row * DM_;
    for (int d = threadIdx.x; d < DM_; d += 256)
        dst[d] = tsrc[d] + psrc[d];
}

// ---------------- layernorm ----------------
__global__ void ln_k(const float* __restrict__ in, long istride,
                     float* __restrict__ out, long ostride,
                     const float* __restrict__ w, const float* __restrict__ bb) {
    __shared__ float red[8];
    __shared__ float s_mean, s_rstd;
    int t = threadIdx.x;
    int row = blockIdx.x;
    const float* src = in + (long)row * istride;
    float v[4];
    float s = 0.f;
#pragma unroll
    for (int i = 0; i < 4; i++) { v[i] = src[t + i*256]; s += v[i]; }
#pragma unroll
    for (int o = 16; o; o >>= 1) s += __shfl_xor_sync(~0u, s, o);
    if ((t & 31) == 0) red[t >> 5] = s;
    __syncthreads();
    if (t < 32) {
        float x = (t < 8) ? red[t] : 0.f;
#pragma unroll
        for (int o = 4; o; o >>= 1) x += __shfl_xor_sync(~0u, x, o);
        if (t == 0) s_mean = x * (1.f/DM_);
    }
    __syncthreads();
    float mean = s_mean;
    float q = 0.f;
#pragma unroll
    for (int i = 0; i < 4; i++) { float d = v[i] - mean; q += d * d; }
#pragma unroll
    for (int o = 16; o; o >>= 1) q += __shfl_xor_sync(~0u, q, o);
    if ((t & 31) == 0) red[t >> 5] = q;
    __syncthreads();
    if (t < 32) {
        float x = (t < 8) ? red[t] : 0.f;
#pragma unroll
        for (int o = 4; o; o >>= 1) x += __shfl_xor_sync(~0u, x, o);
        if (t == 0) s_rstd = rsqrtf(x * (1.f/DM_) + 1e-5f);
    }
    __syncthreads();
    float r = s_rstd;
    float* dst = out + (long)row * ostride;
#pragma unroll
    for (int i = 0; i < 4; i++) {
        int idx = t + i*256;
        dst[idx] = (v[i] - mean) * r * w[idx] + bb[idx];
    }
}

// ---------------- bf16 split helpers ----------------
__device__ __forceinline__ uint2 split2_bf16(float x, float y) {
    __nv_bfloat16 hx = __float2bfloat16(x);
    __nv_bfloat16 hy = __float2bfloat16(y);
    float lx = x - __bfloat162float(hx);
    float ly = y - __bfloat162float(hy);
    __nv_bfloat162 hp = __halves2bfloat162(hx, hy);
    __nv_bfloat162 lp = __halves2bfloat162(__float2bfloat16(lx), __float2bfloat16(ly));
    unsigned hw, lw;
    hw = *reinterpret_cast<unsigned*>(&hp);
    lw = *reinterpret_cast<unsigned*>(&lp);
    return make_uint2(hw, lw);
}

__device__ __forceinline__ void mma_bf16(float* c, const unsigned* a, const unsigned* b) {
    asm volatile(
        "mma.sync.aligned.m16n8k16.row.col.f32.bf16.bf16.f32 "
        "{%0,%1,%2,%3}, {%4,%5,%6,%7}, {%8,%9}, {%0,%1,%2,%3};"
        : "+f"(c[0]), "+f"(c[1]), "+f"(c[2]), "+f"(c[3])
        : "r"(a[0]), "r"(a[1]), "r"(a[2]), "r"(a[3]), "r"(b[0]), "r"(b[1]));
}

// fast softplus: v>20 -> v, else log(1+exp(v)) via MUFU
__device__ __forceinline__ float softplus_f(float v) {
    return (v > 20.f) ? v : __logf(1.f + __expf(v));
}

// deposit (regs -> smem hi/lo split)
#define GEMM_DEPOSIT(AH, AL, BH, BL)                                                   \
    {                                                                                  \
        uint2 s;                                                                       \
        s = split2_bf16(av0.x, av0.y); AH[kp0*SST + r0] = s.x; AL[kp0*SST + r0] = s.y; \
        s = split2_bf16(av0.z, av0.w); AH[(kp0+1)*SST + r0] = s.x; AL[(kp0+1)*SST + r0] = s.y; \
        s = split2_bf16(av1.x, av1.y); AH[kp0*SST + r0+64] = s.x; AL[kp0*SST + r0+64] = s.y; \
        s = split2_bf16(av1.z, av1.w); AH[(kp0+1)*SST + r0+64] = s.x; AL[(kp0+1)*SST + r0+64] = s.y; \
        s = split2_bf16(bv0.x, bv0.y); BH[kp0*SST + r0] = s.x; BL[kp0*SST + r0] = s.y; \
        s = split2_bf16(bv0.z, bv0.w); BH[(kp0+1)*SST + r0] = s.x; BL[(kp0+1)*SST + r0] = s.y; \
        s = split2_bf16(bv1.x, bv1.y); BH[kp0*SST + r0+64] = s.x; BL[kp0*SST + r0+64] = s.y; \
        s = split2_bf16(bv1.z, bv1.w); BH[(kp0+1)*SST + r0+64] = s.x; BL[(kp0+1)*SST + r0+64] = s.y; \
    }

// half compute: i = IBASE, IBASE+1 (loads its own B fragments)
#define GEMM_COMPUTE_HALF(AH, AL, BH, BL, IBASE)                                       \
    {                                                                                  \
        unsigned bh[4][2], bl[4][2];                                                   \
        _Pragma("unroll")                                                              \
        for (int j = 0; j < 4; j++) {                                                  \
            int n = warpN + j*8 + grp;                                                 \
            bh[j][0] = BH[tig*SST + n];                                                \
            bh[j][1] = BH[(tig+4)*SST + n];                                            \
            bl[j][0] = BL[tig*SST + n];                                                \
            bl[j][1] = BL[(tig+4)*SST + n];                                            \
        }                                                                              \
        _Pragma("unroll")                                                              \
        for (int i = IBASE; i < IBASE+2; i++) {                                        \
            int m = warpM + i*16 + grp;                                                \
            unsigned ah[4], al[4];                                                     \
            ah[0] = AH[tig*SST + m];     ah[1] = AH[tig*SST + m + 8];                  \
            ah[2] = AH[(tig+4)*SST + m]; ah[3] = AH[(tig+4)*SST + m + 8];              \
            al[0] = AL[tig*SST + m];     al[1] = AL[tig*SST + m + 8];                  \
            al[2] = AL[(tig+4)*SST + m]; al[3] = AL[(tig+4)*SST + m + 8];              \
            _Pragma("unroll")                                                          \
            for (int j = 0; j < 4; j++) mma_bf16(acc[i][j], ah, bh[j]);                \
            _Pragma("unroll")                                                          \
            for (int j = 0; j < 4; j++) mma_bf16(acc[i][j], ah, bl[j]);                \
            _Pragma("unroll")                                                          \
            for (int j = 0; j < 4; j++) mma_bf16(acc[i][j], al, bh[j]);                \
        }                                                                              \
    }

// one full k-tile body: load(k+1), compute half(k), deposit(k+1), compute half(k)
#define GEMM_KT_BODY(CUR_AH, CUR_AL, CUR_BH, CUR_BL, NXT_AH, NXT_AL, NXT_BH, NXT_BL)   \
    {                                                                                  \
        float4 av0, av1, bv0, bv1;                                                     \
        if (pf) {                                                                      \
            av0 = aOK0 ? *(const float4*)(Ap0 + k0) : z4;                              \
            av1 = aOK1 ? *(const float4*)(Ap1 + k0) : z4;                              \
            bv0 = bOK0 ? *(const float4*)(Wp0 + k0) : z4;                              \
            bv1 = bOK1 ? *(const float4*)(Wp1 + k0) : z4;                              \
        }                                                                              \
        GEMM_COMPUTE_HALF(CUR_AH, CUR_AL, CUR_BH, CUR_BL, 0);                          \
        if (pf) { GEMM_DEPOSIT(NXT_AH, NXT_AL, NXT_BH, NXT_BL); }                      \
        GEMM_COMPUTE_HALF(CUR_AH, CUR_AL, CUR_BH, CUR_BL, 2);                          \
    }

// ---------------- bf16x2 compensated GEMM (double-buffered, latency-hidden) ------------
__global__ __launch_bounds__(256, 2)
void gemm_bf16c(int M, int N, int Kd,
                const float* __restrict__ A, int lda,
                const float* __restrict__ W, int ldb,
                float* __restrict__ C, int ldc,
                const float* __restrict__ bias,
                const float* __restrict__ add, int ldadd,
                int act) {
    __shared__ unsigned Ahp[2][8*SST], Alp[2][8*SST];
    __shared__ unsigned Bhp[2][8*SST], Blp[2][8*SST];
    int tid = threadIdx.x;
    int lane = tid & 31, wid = tid >> 5;
    int warpM = (wid >> 2) * 64;
    int warpN = (wid & 3) * 32;
    int grp = lane >> 2, tig = lane & 3;

    int r0 = tid >> 2;
    int c4 = (tid & 3) * 4;
    int kp0 = c4 >> 1;
    int gAr0 = blockIdx.y * BM + r0, gAr1 = gAr0 + 64;
    int gBr0 = blockIdx.x * BN + r0, gBr1 = gBr0 + 64;
    bool aOK0 = gAr0 < M, aOK1 = gAr1 < M;
    bool bOK0 = gBr0 < N, bOK1 = gBr1 < N;
    const float* Ap0 = A + (long)gAr0 * lda + c4;
    const float* Ap1 = A + (long)gAr1 * lda + c4;
    const float* Wp0 = W + (long)gBr0 * ldb + c4;
    const float* Wp1 = W + (long)gBr1 * ldb + c4;

    float acc[4][4][4];
#pragma unroll
    for (int i = 0; i < 4; i++)
#pragma unroll
        for (int j = 0; j < 4; j++)
#pragma unroll
            for (int q = 0; q < 4; q++) acc[i][j][q] = 0.f;

    const float4 z4 = make_float4(0,0,0,0);

    {   // prologue: stage 0
        float4 av0 = aOK0 ? *(const float4*)(Ap0) : z4;
        float4 av1 = aOK1 ? *(const float4*)(Ap1) : z4;
        float4 bv0 = bOK0 ? *(const float4*)(Wp0) : z4;
        float4 bv1 = bOK1 ? *(const float4*)(Wp1) : z4;
        GEMM_DEPOSIT(Ahp[0], Alp[0], Bhp[0], Blp[0]);
    }
    __syncthreads();

    int nst = Kd / BK;
    for (int kt = 0; kt < nst; kt++) {
        int cur = kt & 1;
        bool pf = (kt + 1) < nst;
        int k0 = (kt + 1) * BK;
        if (cur == 0) {
            GEMM_KT_BODY(Ahp[0], Alp[0], Bhp[0], Blp[0], Ahp[1], Alp[1], Bhp[1], Blp[1]);
        } else {
            GEMM_KT_BODY(Ahp[1], Alp[1], Bhp[1], Blp[1], Ahp[0], Alp[0], Bhp[0], Blp[0]);
        }
        if (pf) __syncthreads();
    }

#pragma unroll
    for (int i = 0; i < 4; i++) {
        int gm0 = blockIdx.y * BM + warpM + i*16 + grp;
#pragma unroll
        for (int j = 0; j < 4; j++) {
            int gn = blockIdx.x * BN + warpN + j*8 + 2*tig;
#pragma unroll
            for (int half = 0; half < 2; half++) {
                int gm = gm0 + half*8;
                if (gm >= M) continue;
#pragma unroll
                for (int q = 0; q < 2; q++) {
                    int n = gn + q;
                    if (n >= N) continue;
                    float v = acc[i][j][half*2 + q];
                    if (bias) v += bias[n];
                    if (act == 1) v = softplus_f(v);
                    if (add) v += add[(long)gm * ldadd + n];
                    C[(long)gm * ldc + n] = v;
                }
            }
        }
    }
}

// ---------------- split-K variant: C += partial (atomicAdd epilogue) ----------------
__global__ __launch_bounds__(256, 2)
void gemm_bf16c_sk(int M, int N, int kcnt,
                   const float* __restrict__ A, int lda,
                   const float* __restrict__ W, int ldb,
                   float* __restrict__ C, int ldc) {
    __shared__ unsigned Ahp[2][8*SST], Alp[2][8*SST];
    __shared__ unsigned Bhp[2][8*SST], Blp[2][8*SST];
    int tid = threadIdx.x;
    int lane = tid & 31, wid = tid >> 5;
    int warpM = (wid >> 2) * 64;
    int warpN = (wid & 3) * 32;
    int grp = lane >> 2, tig = lane & 3;

    long kbeg = (long)blockIdx.z * kcnt;
    A += kbeg; W += kbeg;

    int r0 = tid >> 2;
    int c4 = (tid & 3) * 4;
    int kp0 = c4 >> 1;
    int gAr0 = blockIdx.y * BM + r0, gAr1 = gAr0 + 64;
    int gBr0 = blockIdx.x * BN + r0, gBr1 = gBr0 + 64;
    bool aOK0 = gAr0 < M, aOK1 = gAr1 < M;
    bool bOK0 = gBr0 < N, bOK1 = gBr1 < N;
    const float* Ap0 = A + (long)gAr0 * lda + c4;
    const float* Ap1 = A + (long)gAr1 * lda + c4;
    const float* Wp0 = W + (long)gBr0 * ldb + c4;
    const float* Wp1 = W + (long)gBr1 * ldb + c4;

    float acc[4][4][4];
#pragma unroll
    for (int i = 0; i < 4; i++)
#pragma unroll
        for (int j = 0; j < 4; j++)
#pragma unroll
            for (int q = 0; q < 4; q++) acc[i][j][q] = 0.f;

    const float4 z4 = make_float4(0,0,0,0);

    {   // prologue: stage 0
        float4 av0 = aOK0 ? *(const float4*)(Ap0) : z4;
        float4 av1 = aOK1 ? *(const float4*)(Ap1) : z4;
        float4 bv0 = bOK0 ? *(const float4*)(Wp0) : z4;
        float4 bv1 = bOK1 ? *(const float4*)(Wp1) : z4;
        GEMM_DEPOSIT(Ahp[0], Alp[0], Bhp[0], Blp[0]);
    }
    __syncthreads();

    int nst = kcnt / BK;
    for (int kt = 0; kt < nst; kt++) {
        int cur = kt & 1;
        bool pf = (kt + 1) < nst;
        int k0 = (kt + 1) * BK;
        if (cur == 0) {
            GEMM_KT_BODY(Ahp[0], Alp[0], Bhp[0], Blp[0], Ahp[1], Alp[1], Bhp[1], Blp[1]);
        } else {
            GEMM_KT_BODY(Ahp[1], Alp[1], Bhp[1], Blp[1], Ahp[0], Alp[0], Bhp[0], Blp[0]);
        }
        if (pf) __syncthreads();
    }

#pragma unroll
    for (int i = 0; i < 4; i++) {
        int gm0 = blockIdx.y * BM + warpM + i*16 + grp;
#pragma unroll
        for (int j = 0; j < 4; j++) {
            int gn = blockIdx.x * BN + warpN + j*8 + 2*tig;
#pragma unroll
            for (int half = 0; half < 2; half++) {
                int gm = gm0 + half*8;
                if (gm >= M) continue;
#pragma unroll
                for (int q = 0; q < 2; q++) {
                    int n = gn + q;
                    if (n >= N) continue;
                    atomicAdd(&C[(long)gm * ldc + n], acc[i][j][half*2 + q]);
                }
            }
        }
    }
}

// ---------------- causal depthwise conv (K=4) + SiLU (fast sigmoid) ----------------
__global__ void conv_silu_k(const float* __restrict__ xz, const float* __restrict__ cw,
                            const float* __restrict__ cb, float* __restrict__ xb) {
    long idx = (long)blockIdx.x * 256 + threadIdx.x;
    int d = idx & (DI_ - 1);
    long bl = idx >> 11;
    int l = (int)(bl & (L_ - 1));
    float acc = cb[d];
#pragma unroll
    for (int k = 0; k < K_; k++) {
        int lp = l + k - (K_ - 1);
        if (lp >= 0)
            acc = fmaf(cw[d*K_ + k], xz[(bl + (k - (K_-1))) * (2*DI_) + d], acc);
    }
    acc = __fdividef(acc, 1.f + __expf(-acc));
    xb[idx] = acc;
}

// ---------------- selective SSM scan + D skip + z-gating (fast exp) ----------------
__global__ void ssm_scan_k(const float* __restrict__ xb, const float* __restrict__ xp,
                           const float* __restrict__ dl, const float* __restrict__ xz,
                           const float* __restrict__ Alog, const float* __restrict__ Dp,
                           float* __restrict__ y) {
    int t = threadIdx.x;
    int g = t >> 4, lane = t & 15;
    int ch = blockIdx.x * 16 + g;
    int b = ch >> 11;
    int d = ch & (DI_ - 1);
    float A = -__expf(Alog[d*N_ + lane]);
    float Dv = Dp[d];
    float h = 0.f;
    long rowbase = (long)b * L_;
    const float* dlp = dl + rowbase*DI_ + d;
    const float* xbp = xb + rowbase*DI_ + d;
    const float* Bp  = xp + rowbase*XPW_ + DTR_ + lane;
    const float* zp  = xz + rowbase*(2*DI_) + DI_ + d;
    float* yp = y + rowbase*DI_ + d;
    for (int l = 0; l < L_; l++) {
        float dv = dlp[(long)l*DI_];
        float xv = xbp[(long)l*DI_];
        float Bv = Bp[(long)l*XPW_];
        float Cv = Bp[(long)l*XPW_ + N_];
        h = fmaf(__expf(dv * A), h, dv * Bv * xv);
        float c = h * Cv;
        c += __shfl_xor_sync(~0u, c, 8);
        c += __shfl_xor_sync(~0u, c, 4);
        c += __shfl_xor_sync(~0u, c, 2);
        c += __shfl_xor_sync(~0u, c, 1);
        if (lane == 0) {
            float z = zp[(long)l*(2*DI_)];
            float yv = c + xv * Dv;
            yp[(long)l*DI_] = yv * __fdividef(z, 1.f + __expf(-z));
        }
    }
}

// ---------------- head ----------------
__global__ void head_k(const float* __restrict__ fin, const float* __restrict__ hw,
                       float* __restrict__ out) {
    int wid = blockIdx.x * 8 + (threadIdx.x >> 5);
    int lane = threadIdx.x & 31;
    if (wid >= B_ * P_) return;
    int b = wid / P_, p = wid % P_;
    const float* a = fin + (long)b * DM_;
    const float* w = hw + (long)p * DM_;
    float s = 0.f;
    for (int k = lane; k < DM_; k += 32) s = fmaf(a[k], w[k], s);
#pragma unroll
    for (int o = 16; o; o >>= 1) s += __shfl_xor_sync(~0u, s, o);
    if (lane == 0) out[wid] = s;
}

// ---------------- launch ----------------
extern "C" void kernel_launch(void* const* d_in, const int* in_sizes, int n_in,
                              void* d_out, int out_size) {
    const int*   tokens    = (const int*)  d_in[0];
    const float* tok_emb   = (const float*)d_in[1];
    const float* pos_emb   = (const float*)d_in[2];
    const float* ln_w      = (const float*)d_in[3];
    const float* ln_b      = (const float*)d_in[4];
    const float* in_proj_w = (const float*)d_in[5];
    const float* conv_w    = (const float*)d_in[6];
    const float* conv_b    = (const float*)d_in[7];
    const float* xproj_w   = (const float*)d_in[8];
    const float* dt_w      = (const float*)d_in[9];
    const float* dt_b      = (const float*)d_in[10];
    const float* A_log     = (const float*)d_in[11];
    const float* D_param   = (const float*)d_in[12];
    const float* out_proj_w= (const float*)d_in[13];
    const float* fnorm_w   = (const float*)d_in[14];
    const float* fnorm_b   = (const float*)d_in[15];
    const float* head_w    = (const float*)d_in[16];
    float* out = (float*)d_out;

    void *ph, *px, *pxz, *pxb, *pxp, *pdl, *py, *pfin;
    cudaGetSymbolAddress(&ph,  g_h);
    cudaGetSymbolAddress(&px,  g_x);
    cudaGetSymbolAddress(&pxz, g_xz);
    cudaGetSymbolAddress(&pxb, g_xb);
    cudaGetSymbolAddress(&pxp, g_xp);
    cudaGetSymbolAddress(&pdl, g_dl);
    cudaGetSymbolAddress(&py,  g_y);
    cudaGetSymbolAddress(&pfin,g_fin);
    float* h  = (float*)ph;   float* x  = (float*)px;
    float* xz = (float*)pxz;  float* xb = (float*)pxb;
    float* xp = (float*)pxp;  float* dl = (float*)pdl;
    float* y  = (float*)py;   float* fin= (float*)pfin;

    embed_k<<<M_TOK, 256>>>(tokens, tok_emb, pos_emb, h);

    for (int i = 0; i < NL_; i++) {
        ln_k<<<M_TOK, 256>>>(h, DM_, x, DM_, ln_w + i*DM_, ln_b + i*DM_);
        // in_proj: 2048 x 4096 x 1024 (512 CTAs)
        gemm_bf16c<<<dim3(32, 16), 256>>>(M_TOK, 2*DI_, DM_,
            x, DM_, in_proj_w + (long)i*2*DI_*DM_, DM_,
            xz, 2*DI_, nullptr, nullptr, 0, 0);
        conv_silu_k<<<(M_TOK*DI_)/256, 256>>>(xz, conv_w + (long)i*DI_*K_, conv_b + (long)i*DI_, xb);
        // xproj: 2048 x 160 x 2048 — split-K 8, atomic accumulate into zeroed xp
        zero_k<<<(M_TOK*XPW_/4 + 255)/256, 256>>>(xp, M_TOK*XPW_/4);
        gemm_bf16c_sk<<<dim3(2, 16, 8), 256>>>(M_TOK, XPW_, DI_/8,
            xb, DI_, xproj_w + (long)i*XPW_*DI_, DI_,
            xp, XPW_);
        // delta = softplus(dt_r @ dtw.T + dtb): 2048 x 2048 x 128
        gemm_bf16c<<<dim3(16, 16), 256>>>(M_TOK, DI_, DTR_,
            xp, XPW_, dt_w + (long)i*DI_*DTR_, DTR_,
            dl, DI_, dt_b + (long)i*DI_, nullptr, 0, 1);
        ssm_scan_k<<<(B_*DI_)/16, 256>>>(xb, xp, dl, xz,
            A_log + (long)i*DI_*N_, D_param + (long)i*DI_, y);
        // out_proj + residual: 2048 x 1024 x 2048 — split-K 2, h already holds residual
        gemm_bf16c_sk<<<dim3(8, 16, 2), 256>>>(M_TOK, DM_, DI_/2,
            y, DI_, out_proj_w + (long)i*DM_*DI_, DI_,
            h, DM_);
    }

    ln_k<<<B_, 256>>>(h + (long)(L_-1)*DM_, (long)L_*DM_, fin, DM_, fnorm_w, fnorm_b);
    head_k<<<P_, 256>>>(fin, head_w, out);
}

// round 15
// speedup vs baseline: 1.1594x; 1.1594x over previous
#include <cuda_runtime.h>
#include <cuda_bf16.h>
#include <math.h>

// Problem constants
#define B_  8
#define L_  256
#define DM_ 1024
#define DI_ 2048
#define N_  16
#define K_  4
#define NL_ 4
#define DTR_ 128
#define P_  97
#define M_TOK (B_*L_)          // 2048 token rows
#define XPW_ (DTR_ + 2*N_)     // 160

// GEMM tiling
#define BM 128
#define BN 128
#define BK 32                  // 32-k tiles (2 x 16-k chunks)
#define SST 132                // smem row stride in words ([kp][m] layout, kp = k/2)
#define STGW (16*SST)          // words per stage per array (16 kp rows)
#define GEMM_DSM (8*STGW*4)    // 4 arrays x 2 stages = 67584 B

// ---------------- scratch (static device globals; no allocation) ----------------
__device__ __align__(16) float g_h [M_TOK*DM_];
__device__ __align__(16) float g_x [M_TOK*DM_];
__device__ __align__(16) float g_xz[M_TOK*2*DI_];
__device__ __align__(16) float g_xb[M_TOK*DI_];
__device__ __align__(16) float g_xp[M_TOK*XPW_];
__device__ __align__(16) float g_dl[M_TOK*DI_];
__device__ __align__(16) float g_y [M_TOK*DI_];
__device__ __align__(16) float g_fin[B_*DM_];

// ---------------- small utils ----------------
__global__ void zero_k(float* __restrict__ p, int n4) {
    int i = blockIdx.x * 256 + threadIdx.x;
    if (i < n4) reinterpret_cast<float4*>(p)[i] = make_float4(0,0,0,0);
}

// ---------------- embedding ----------------
__global__ void embed_k(const int* __restrict__ tok, const float* __restrict__ te,
                        const float* __restrict__ pe, float* __restrict__ h) {
    int row = blockIdx.x;
    int l = row & (L_ - 1);
    int t = tok[row];
    const float* tsrc = te + (long)t * DM_;
    const float* psrc = pe + (long)l * DM_;
    float* dst = h + (long)row * DM_;
    for (int d = threadIdx.x; d < DM_; d += 256)
        dst[d] = tsrc[d] + psrc[d];
}

// ---------------- layernorm ----------------
__global__ void ln_k(const float* __restrict__ in, long istride,
                     float* __restrict__ out, long ostride,
                     const float* __restrict__ w, const float* __restrict__ bb) {
    __shared__ float red[8];
    __shared__ float s_mean, s_rstd;
    int t = threadIdx.x;
    int row = blockIdx.x;
    const float* src = in + (long)row * istride;
    float v[4];
    float s = 0.f;
#pragma unroll
    for (int i = 0; i < 4; i++) { v[i] = src[t + i*256]; s += v[i]; }
#pragma unroll
    for (int o = 16; o; o >>= 1) s += __shfl_xor_sync(~0u, s, o);
    if ((t & 31) == 0) red[t >> 5] = s;
    __syncthreads();
    if (t < 32) {
        float x = (t < 8) ? red[t] : 0.f;
#pragma unroll
        for (int o = 4; o; o >>= 1) x += __shfl_xor_sync(~0u, x, o);
        if (t == 0) s_mean = x * (1.f/DM_);
    }
    __syncthreads();
    float mean = s_mean;
    float q = 0.f;
#pragma unroll
    for (int i = 0; i < 4; i++) { float d = v[i] - mean; q += d * d; }
#pragma unroll
    for (int o = 16; o; o >>= 1) q += __shfl_xor_sync(~0u, q, o);
    if ((t & 31) == 0) red[t >> 5] = q;
    __syncthreads();
    if (t < 32) {
        float x = (t < 8) ? red[t] : 0.f;
#pragma unroll
        for (int o = 4; o; o >>= 1) x += __shfl_xor_sync(~0u, x, o);
        if (t == 0) s_rstd = rsqrtf(x * (1.f/DM_) + 1e-5f);
    }
    __syncthreads();
    float r = s_rstd;
    float* dst = out + (long)row * ostride;
#pragma unroll
    for (int i = 0; i < 4; i++) {
        int idx = t + i*256;
        dst[idx] = (v[i] - mean) * r * w[idx] + bb[idx];
    }
}

// ---------------- bf16 split helpers ----------------
__device__ __forceinline__ uint2 split2_bf16(float x, float y) {
    __nv_bfloat16 hx = __float2bfloat16(x);
    __nv_bfloat16 hy = __float2bfloat16(y);
    float lx = x - __bfloat162float(hx);
    float ly = y - __bfloat162float(hy);
    __nv_bfloat162 hp = __halves2bfloat162(hx, hy);
    __nv_bfloat162 lp = __halves2bfloat162(__float2bfloat16(lx), __float2bfloat16(ly));
    unsigned hw, lw;
    hw = *reinterpret_cast<unsigned*>(&hp);
    lw = *reinterpret_cast<unsigned*>(&lp);
    return make_uint2(hw, lw);
}

__device__ __forceinline__ void mma_bf16(float* c, const unsigned* a, const unsigned* b) {
    asm volatile(
        "mma.sync.aligned.m16n8k16.row.col.f32.bf16.bf16.f32 "
        "{%0,%1,%2,%3}, {%4,%5,%6,%7}, {%8,%9}, {%0,%1,%2,%3};"
        : "+f"(c[0]), "+f"(c[1]), "+f"(c[2]), "+f"(c[3])
        : "r"(a[0]), "r"(a[1]), "r"(a[2]), "r"(a[3]), "r"(b[0]), "r"(b[1]));
}

// fast softplus: v>20 -> v, else log(1+exp(v)) via MUFU
__device__ __forceinline__ float softplus_f(float v) {
    return (v > 20.f) ? v : __logf(1.f + __expf(v));
}

// load one 16-k chunk at global col (k0 + COFF) and deposit into rows ROWB+kp0..+1
#define GEMM_LOAD_DEPOSIT(AH, AL, BH, BL, KOFF, ROWB)                                  \
    {                                                                                  \
        float4 av0 = aOK0 ? *(const float4*)(Ap0 + (KOFF)) : z4;                       \
        float4 av1 = aOK1 ? *(const float4*)(Ap1 + (KOFF)) : z4;                       \
        float4 bv0 = bOK0 ? *(const float4*)(Wp0 + (KOFF)) : z4;                       \
        float4 bv1 = bOK1 ? *(const float4*)(Wp1 + (KOFF)) : z4;                       \
        uint2 s;                                                                       \
        s = split2_bf16(av0.x, av0.y); AH[((ROWB)+kp0)*SST + r0] = s.x; AL[((ROWB)+kp0)*SST + r0] = s.y; \
        s = split2_bf16(av0.z, av0.w); AH[((ROWB)+kp0+1)*SST + r0] = s.x; AL[((ROWB)+kp0+1)*SST + r0] = s.y; \
        s = split2_bf16(av1.x, av1.y); AH[((ROWB)+kp0)*SST + r0+64] = s.x; AL[((ROWB)+kp0)*SST + r0+64] = s.y; \
        s = split2_bf16(av1.z, av1.w); AH[((ROWB)+kp0+1)*SST + r0+64] = s.x; AL[((ROWB)+kp0+1)*SST + r0+64] = s.y; \
        s = split2_bf16(bv0.x, bv0.y); BH[((ROWB)+kp0)*SST + r0] = s.x; BL[((ROWB)+kp0)*SST + r0] = s.y; \
        s = split2_bf16(bv0.z, bv0.w); BH[((ROWB)+kp0+1)*SST + r0] = s.x; BL[((ROWB)+kp0+1)*SST + r0] = s.y; \
        s = split2_bf16(bv1.x, bv1.y); BH[((ROWB)+kp0)*SST + r0+64] = s.x; BL[((ROWB)+kp0)*SST + r0+64] = s.y; \
        s = split2_bf16(bv1.z, bv1.w); BH[((ROWB)+kp0+1)*SST + r0+64] = s.x; BL[((ROWB)+kp0+1)*SST + r0+64] = s.y; \
    }

// one 16-k compute step from kp rows KPOFF..KPOFF+7
#define GEMM_COMPUTE(AH, AL, BH, BL, KPOFF)                                            \
    {                                                                                  \
        int krow = (KPOFF) + tig;                                                      \
        unsigned bh[4][2], bl[4][2];                                                   \
        _Pragma("unroll")                                                              \
        for (int j = 0; j < 4; j++) {                                                  \
            int n = warpN + j*8 + grp;                                                 \
            bh[j][0] = BH[krow*SST + n];                                               \
            bh[j][1] = BH[(krow+4)*SST + n];                                           \
            bl[j][0] = BL[krow*SST + n];                                               \
            bl[j][1] = BL[(krow+4)*SST + n];                                           \
        }                                                                              \
        _Pragma("unroll")                                                              \
        for (int i = 0; i < 4; i++) {                                                  \
            int m = warpM + i*16 + grp;                                                \
            unsigned ah[4], al[4];                                                     \
            ah[0] = AH[krow*SST + m];     ah[1] = AH[krow*SST + m + 8];                \
            ah[2] = AH[(krow+4)*SST + m]; ah[3] = AH[(krow+4)*SST + m + 8];            \
            al[0] = AL[krow*SST + m];     al[1] = AL[krow*SST + m + 8];                \
            al[2] = AL[(krow+4)*SST + m]; al[3] = AL[(krow+4)*SST + m + 8];            \
            _Pragma("unroll")                                                          \
            for (int j = 0; j < 4; j++) mma_bf16(acc[i][j], ah, bh[j]);                \
            _Pragma("unroll")                                                          \
            for (int j = 0; j < 4; j++) mma_bf16(acc[i][j], ah, bl[j]);                \
            _Pragma("unroll")                                                          \
            for (int j = 0; j < 4; j++) mma_bf16(acc[i][j], al, bh[j]);                \
        }                                                                              \
    }

// common GEMM preamble (indices + pointers + acc init + stage-0 deposit)
#define GEMM_PREAMBLE(ABASE, WBASE, LDA, LDB, MM, NN)                                  \
    extern __shared__ unsigned dynsm[];                                                \
    unsigned* AHb = dynsm;                                                             \
    unsigned* ALb = dynsm + 2*STGW;                                                    \
    unsigned* BHb = dynsm + 4*STGW;                                                    \
    unsigned* BLb = dynsm + 6*STGW;                                                    \
    int tid = threadIdx.x;                                                             \
    int lane = tid & 31, wid = tid >> 5;                                               \
    int warpM = (wid >> 2) * 64;                                                       \
    int warpN = (wid & 3) * 32;                                                        \
    int grp = lane >> 2, tig = lane & 3;                                               \
    int r0 = tid >> 2;                                                                 \
    int c4 = (tid & 3) * 4;                                                            \
    int kp0 = c4 >> 1;                                                                 \
    int gAr0 = blockIdx.y * BM + r0, gAr1 = gAr0 + 64;                                 \
    int gBr0 = blockIdx.x * BN + r0, gBr1 = gBr0 + 64;                                 \
    bool aOK0 = gAr0 < (MM), aOK1 = gAr1 < (MM);                                       \
    bool bOK0 = gBr0 < (NN), bOK1 = gBr1 < (NN);                                       \
    const float* Ap0 = (ABASE) + (long)gAr0 * (LDA) + c4;                              \
    const float* Ap1 = (ABASE) + (long)gAr1 * (LDA) + c4;                              \
    const float* Wp0 = (WBASE) + (long)gBr0 * (LDB) + c4;                              \
    const float* Wp1 = (WBASE) + (long)gBr1 * (LDB) + c4;                              \
    float acc[4][4][4];                                                                \
    _Pragma("unroll")                                                                  \
    for (int i = 0; i < 4; i++)                                                        \
        _Pragma("unroll")                                                              \
        for (int j = 0; j < 4; j++)                                                    \
            _Pragma("unroll")                                                          \
            for (int q = 0; q < 4; q++) acc[i][j][q] = 0.f;                            \
    const float4 z4 = make_float4(0,0,0,0);                                            \
    GEMM_LOAD_DEPOSIT(AHb, ALb, BHb, BLb, 0, 0);                                       \
    GEMM_LOAD_DEPOSIT(AHb, ALb, BHb, BLb, 16, 8);                                      \
    __syncthreads();

#define GEMM_MAINLOOP(NST)                                                             \
    for (int kt = 0; kt < (NST); kt++) {                                               \
        int cur = kt & 1, nxt = cur ^ 1;                                               \
        bool pf = (kt + 1) < (NST);                                                    \
        unsigned* cAH = AHb + cur*STGW; unsigned* cAL = ALb + cur*STGW;                \
        unsigned* cBH = BHb + cur*STGW; unsigned* cBL = BLb + cur*STGW;                \
        if (pf) {                                                                      \
            int k0 = (kt + 1) * BK;                                                    \
            unsigned* nAH = AHb + nxt*STGW; unsigned* nAL = ALb + nxt*STGW;            \
            unsigned* nBH = BHb + nxt*STGW; unsigned* nBL = BLb + nxt*STGW;            \
            GEMM_LOAD_DEPOSIT(nAH, nAL, nBH, nBL, k0, 0);                              \
            GEMM_LOAD_DEPOSIT(nAH, nAL, nBH, nBL, k0 + 16, 8);                         \
        }                                                                              \
        GEMM_COMPUTE(cAH, cAL, cBH, cBL, 0);                                           \
        GEMM_COMPUTE(cAH, cAL, cBH, cBL, 8);                                           \
        if (pf) __syncthreads();                                                       \
    }

// ---------------- bf16x2 compensated GEMM (BK=32, deposit-early) ----------------
__global__ __launch_bounds__(256, 2)
void gemm_bf16c(int M, int N, int Kd,
                const float* __restrict__ A, int lda,
                const float* __restrict__ W, int ldb,
                float* __restrict__ C, int ldc,
                const float* __restrict__ bias,
                const float* __restrict__ add, int ldadd,
                int act) {
    GEMM_PREAMBLE(A, W, lda, ldb, M, N);
    GEMM_MAINLOOP(Kd / BK);

#pragma unroll
    for (int i = 0; i < 4; i++) {
        int gm0 = blockIdx.y * BM + warpM + i*16 + grp;
#pragma unroll
        for (int j = 0; j < 4; j++) {
            int gn = blockIdx.x * BN + warpN + j*8 + 2*tig;
#pragma unroll
            for (int half = 0; half < 2; half++) {
                int gm = gm0 + half*8;
                if (gm >= M) continue;
#pragma unroll
                for (int q = 0; q < 2; q++) {
                    int n = gn + q;
                    if (n >= N) continue;
                    float v = acc[i][j][half*2 + q];
                    if (bias) v += bias[n];
                    if (act == 1) v = softplus_f(v);
                    if (add) v += add[(long)gm * ldadd + n];
                    C[(long)gm * ldc + n] = v;
                }
            }
        }
    }
}

// ---------------- split-K variant: C += partial (atomicAdd epilogue) ----------------
__global__ __launch_bounds__(256, 2)
void gemm_bf16c_sk(int M, int N, int kcnt,
                   const float* __restrict__ A, int lda,
                   const float* __restrict__ W, int ldb,
                   float* __restrict__ C, int ldc) {
    long kbeg = (long)blockIdx.z * kcnt;
    const float* Ab = A + kbeg;
    const float* Wb = W + kbeg;
    GEMM_PREAMBLE(Ab, Wb, lda, ldb, M, N);
    GEMM_MAINLOOP(kcnt / BK);

#pragma unroll
    for (int i = 0; i < 4; i++) {
        int gm0 = blockIdx.y * BM + warpM + i*16 + grp;
#pragma unroll
        for (int j = 0; j < 4; j++) {
            int gn = blockIdx.x * BN + warpN + j*8 + 2*tig;
#pragma unroll
            for (int half = 0; half < 2; half++) {
                int gm = gm0 + half*8;
                if (gm >= M) continue;
#pragma unroll
                for (int q = 0; q < 2; q++) {
                    int n = gn + q;
                    if (n >= N) continue;
                    atomicAdd(&C[(long)gm * ldc + n], acc[i][j][half*2 + q]);
                }
            }
        }
    }
}

// ---------------- causal depthwise conv (K=4) + SiLU (fast sigmoid) ----------------
__global__ void conv_silu_k(const float* __restrict__ xz, const float* __restrict__ cw,
                            const float* __restrict__ cb, float* __restrict__ xb) {
    long idx = (long)blockIdx.x * 256 + threadIdx.x;
    int d = idx & (DI_ - 1);
    long bl = idx >> 11;
    int l = (int)(bl & (L_ - 1));
    float acc = cb[d];
#pragma unroll
    for (int k = 0; k < K_; k++) {
        int lp = l + k - (K_ - 1);
        if (lp >= 0)
            acc = fmaf(cw[d*K_ + k], xz[(bl + (k - (K_-1))) * (2*DI_) + d], acc);
    }
    acc = __fdividef(acc, 1.f + __expf(-acc));
    xb[idx] = acc;
}

// ---------------- selective SSM scan + D skip + z-gating (fast exp) ----------------
__global__ void ssm_scan_k(const float* __restrict__ xb, const float* __restrict__ xp,
                           const float* __restrict__ dl, const float* __restrict__ xz,
                           const float* __restrict__ Alog, const float* __restrict__ Dp,
                           float* __restrict__ y) {
    int t = threadIdx.x;
    int g = t >> 4, lane = t & 15;
    int ch = blockIdx.x * 16 + g;
    int b = ch >> 11;
    int d = ch & (DI_ - 1);
    float A = -__expf(Alog[d*N_ + lane]);
    float Dv = Dp[d];
    float h = 0.f;
    long rowbase = (long)b * L_;
    const float* dlp = dl + rowbase*DI_ + d;
    const float* xbp = xb + rowbase*DI_ + d;
    const float* Bp  = xp + rowbase*XPW_ + DTR_ + lane;
    const float* zp  = xz + rowbase*(2*DI_) + DI_ + d;
    float* yp = y + rowbase*DI_ + d;
    for (int l = 0; l < L_; l++) {
        float dv = dlp[(long)l*DI_];
        float xv = xbp[(long)l*DI_];
        float Bv = Bp[(long)l*XPW_];
        float Cv = Bp[(long)l*XPW_ + N_];
        h = fmaf(__expf(dv * A), h, dv * Bv * xv);
        float c = h * Cv;
        c += __shfl_xor_sync(~0u, c, 8);
        c += __shfl_xor_sync(~0u, c, 4);
        c += __shfl_xor_sync(~0u, c, 2);
        c += __shfl_xor_sync(~0u, c, 1);
        if (lane == 0) {
            float z = zp[(long)l*(2*DI_)];
            float yv = c + xv * Dv;
            yp[(long)l*DI_] = yv * __fdividef(z, 1.f + __expf(-z));
        }
    }
}

// ---------------- head ----------------
__global__ void head_k(const float* __restrict__ fin, const float* __restrict__ hw,
                       float* __restrict__ out) {
    int wid = blockIdx.x * 8 + (threadIdx.x >> 5);
    int lane = threadIdx.x & 31;
    if (wid >= B_ * P_) return;
    int b = wid / P_, p = wid % P_;
    const float* a = fin + (long)b * DM_;
    const float* w = hw + (long)p * DM_;
    float s = 0.f;
    for (int k = lane; k < DM_; k += 32) s = fmaf(a[k], w[k], s);
#pragma unroll
    for (int o = 16; o; o >>= 1) s += __shfl_xor_sync(~0u, s, o);
    if (lane == 0) out[wid] = s;
}

// ---------------- launch ----------------
extern "C" void kernel_launch(void* const* d_in, const int* in_sizes, int n_in,
                              void* d_out, int out_size) {
    const int*   tokens    = (const int*)  d_in[0];
    const float* tok_emb   = (const float*)d_in[1];
    const float* pos_emb   = (const float*)d_in[2];
    const float* ln_w      = (const float*)d_in[3];
    const float* ln_b      = (const float*)d_in[4];
    const float* in_proj_w = (const float*)d_in[5];
    const float* conv_w    = (const float*)d_in[6];
    const float* conv_b    = (const float*)d_in[7];
    const float* xproj_w   = (const float*)d_in[8];
    const float* dt_w      = (const float*)d_in[9];
    const float* dt_b      = (const float*)d_in[10];
    const float* A_log     = (const float*)d_in[11];
    const float* D_param   = (const float*)d_in[12];
    const float* out_proj_w= (const float*)d_in[13];
    const float* fnorm_w   = (const float*)d_in[14];
    const float* fnorm_b   = (const float*)d_in[15];
    const float* head_w    = (const float*)d_in[16];
    float* out = (float*)d_out;

    // host-side attribute config (graph-safe, idempotent)
    cudaFuncSetAttribute(gemm_bf16c,    cudaFuncAttributeMaxDynamicSharedMemorySize, GEMM_DSM);
    cudaFuncSetAttribute(gemm_bf16c_sk, cudaFuncAttributeMaxDynamicSharedMemorySize, GEMM_DSM);

    void *ph, *px, *pxz, *pxb, *pxp, *pdl, *py, *pfin;
    cudaGetSymbolAddress(&ph,  g_h);
    cudaGetSymbolAddress(&px,  g_x);
    cudaGetSymbolAddress(&pxz, g_xz);
    cudaGetSymbolAddress(&pxb, g_xb);
    cudaGetSymbolAddress(&pxp, g_xp);
    cudaGetSymbolAddress(&pdl, g_dl);
    cudaGetSymbolAddress(&py,  g_y);
    cudaGetSymbolAddress(&pfin,g_fin);
    float* h  = (float*)ph;   float* x  = (float*)px;
    float* xz = (float*)pxz;  float* xb = (float*)pxb;
    float* xp = (float*)pxp;  float* dl = (float*)pdl;
    float* y  = (float*)py;   float* fin= (float*)pfin;

    embed_k<<<M_TOK, 256>>>(tokens, tok_emb, pos_emb, h);

    for (int i = 0; i < NL_; i++) {
        ln_k<<<M_TOK, 256>>>(h, DM_, x, DM_, ln_w + i*DM_, ln_b + i*DM_);
        // in_proj: 2048 x 4096 x 1024 (512 CTAs)
        gemm_bf16c<<<dim3(32, 16), 256, GEMM_DSM>>>(M_TOK, 2*DI_, DM_,
            x, DM_, in_proj_w + (long)i*2*DI_*DM_, DM_,
            xz, 2*DI_, nullptr, nullptr, 0, 0);
        conv_silu_k<<<(M_TOK*DI_)/256, 256>>>(xz, conv_w + (long)i*DI_*K_, conv_b + (long)i*DI_, xb);
        // xproj: 2048 x 160 x 2048 — split-K 8 (kcnt=256), atomic into zeroed xp
        zero_k<<<(M_TOK*XPW_/4 + 255)/256, 256>>>(xp, M_TOK*XPW_/4);
        gemm_bf16c_sk<<<dim3(2, 16, 8), 256, GEMM_DSM>>>(M_TOK, XPW_, DI_/8,
            xb, DI_, xproj_w + (long)i*XPW_*DI_, DI_,
            xp, XPW_);
        // delta = softplus(dt_r @ dtw.T + dtb): 2048 x 2048 x 128
        gemm_bf16c<<<dim3(16, 16), 256, GEMM_DSM>>>(M_TOK, DI_, DTR_,
            xp, XPW_, dt_w + (long)i*DI_*DTR_, DTR_,
            dl, DI_, dt_b + (long)i*DI_, nullptr, 0, 1);
        ssm_scan_k<<<(B_*DI_)/16, 256>>>(xb, xp, dl, xz,
            A_log + (long)i*DI_*N_, D_param + (long)i*DI_, y);
        // out_proj + residual: split-K 2 (kcnt=1024), atomic into h (holds residual)
        gemm_bf16c_sk<<<dim3(8, 16, 2), 256, GEMM_DSM>>>(M_TOK, DM_, DI_/2,
            y, DI_, out_proj_w + (long)i*DM_*DI_, DI_,
            h, DM_);
    }

    ln_k<<<B_, 256>>>(h + (long)(L_-1)*DM_, (long)L_*DM_, fin, DM_, fnorm_w, fnorm_b);
    head_k<<<P_, 256>>>(fin, head_w, out);
}